// round 13
// baseline (speedup 1.0000x reference)
#include <cuda_runtime.h>
#include <cuda_bf16.h>
#include <math.h>
#include <stdint.h>

#define BB 4
#define TT 1024
#define HH 4
#define NN_ 4096
#define DD 256
#define DH 1024
#define LL 6
#define VV 256
#define EPS 1e-5f

// ---------------------------------------------------------------------------
// Scratch (device globals)
// ---------------------------------------------------------------------------
__device__ float g_v[BB * TT * DD];
__device__ float g_x[BB * HH * TT * DH];
__device__ float g_w2[BB * HH * DD * DH];
__device__ float g_a[BB * HH * TT * DD];
__device__ float g_ye[BB * TT * NN_];
__device__ float g_z[4 * BB * TT * DD];
__device__ float g_cos[TT * DH];
__device__ float g_sin[TT * DH];

// int8 quantized operands (h, l) + per-row scales
__device__ int8_t q_v_h[BB * TT * DD],      q_v_l[BB * TT * DD];
__device__ int8_t q_vT_h[BB * DD * TT],     q_vT_l[BB * DD * TT];
__device__ int8_t q_x_h[BB * HH * TT * DH],  q_x_l[BB * HH * TT * DH];
__device__ int8_t q_xr_h[BB * HH * TT * DH], q_xr_l[BB * HH * TT * DH];
__device__ int8_t q_xrT_h[BB * HH * DH * TT], q_xrT_l[BB * HH * DH * TT];
__device__ int8_t q_w2_h[BB * HH * DD * DH], q_w2_l[BB * HH * DD * DH];
__device__ int8_t q_a_h[BB * HH * TT * DD],  q_a_l[BB * HH * TT * DD];
__device__ int8_t q_ye_h[BB * TT * NN_],     q_ye_l[BB * TT * NN_];
__device__ int8_t q_dxT_h[HH * DH * DD],     q_dxT_l[HH * DH * DD];
__device__ int8_t q_dyT_h[HH * DH * DD],     q_dyT_l[HH * DH * DD];
__device__ int8_t q_eT_h[DD * NN_],          q_eT_l[DD * NN_];
__device__ int8_t q_roT_h[VV * DD],          q_roT_l[VV * DD];

__device__ float sc_v[BB * TT];
__device__ float sc_vT[BB * DD];
__device__ float sc_x[BB * HH * TT];
__device__ float sc_xr[BB * HH * TT];
__device__ float sc_xrT[BB * HH * DH];
__device__ float sc_w2[BB * HH * DD];
__device__ float sc_a[BB * HH * TT];
__device__ float sc_ye[BB * TT];
__device__ float sc_dx[HH * DH];
__device__ float sc_dy[HH * DH];
__device__ float sc_e[DD];
__device__ float sc_ro[VV];

// ---------------------------------------------------------------------------
// PTX helpers
// ---------------------------------------------------------------------------
__device__ __forceinline__ uint32_t smem_to_u32(const void* p) {
    uint32_t a;
    asm("{ .reg .u64 t; cvta.to.shared.u64 t, %1; cvt.u32.u64 %0, t; }" : "=r"(a) : "l"(p));
    return a;
}
__device__ __forceinline__ void cp16(uint32_t dst, const void* src) {
    asm volatile("cp.async.cg.shared.global [%0], [%1], 16;" :: "r"(dst), "l"(src));
}
#define CP_COMMIT() asm volatile("cp.async.commit_group;" ::: "memory")
#define CP_WAIT0() asm volatile("cp.async.wait_group 0;" ::: "memory")
#define CP_WAIT1() asm volatile("cp.async.wait_group 1;" ::: "memory")
#define CP_WAIT2() asm volatile("cp.async.wait_group 2;" ::: "memory")

__device__ __forceinline__ void ldsm_x4(uint32_t* r, uint32_t addr) {
    asm volatile("ldmatrix.sync.aligned.m8n8.x4.shared.b16 {%0,%1,%2,%3}, [%4];"
                 : "=r"(r[0]), "=r"(r[1]), "=r"(r[2]), "=r"(r[3]) : "r"(addr));
}
__device__ __forceinline__ void mma_s8(int* d, const uint32_t* a, const uint32_t* b) {
    asm volatile(
        "mma.sync.aligned.m16n8k32.row.col.s32.s8.s8.s32 "
        "{%0,%1,%2,%3}, {%4,%5,%6,%7}, {%8,%9}, {%0,%1,%2,%3};"
        : "+r"(d[0]), "+r"(d[1]), "+r"(d[2]), "+r"(d[3])
        : "r"(a[0]), "r"(a[1]), "r"(a[2]), "r"(a[3]), "r"(b[0]), "r"(b[1]));
}

__device__ __forceinline__ void quant2(float u, int& h, int& l) {
    h = __float2int_rn(u);
    if (h > 127) h = 127; else if (h < -127) h = -127;
    l = __float2int_rn((u - (float)h) * 256.0f);
    if (l > 127) l = 127; else if (l < -127) l = -127;
}

// ---------------------------------------------------------------------------
// int8 two-level GEMM.
// EPI 0: acc; 1: relu; 2: relu*AUX(fp32); 3: relu*AUX(int8 h/l + row scale).
// ---------------------------------------------------------------------------
#define TILE_B 8192
#define NBUF 4
#define SMEM_SZ (NBUF * 4 * TILE_B)
__device__ __forceinline__ uint32_t tile_addr(uint32_t sb, int buf, int which) {
    return sb + (uint32_t)((buf * 4 + which) * TILE_B);
}

template <int EPI>
__global__ void __launch_bounds__(256)
mm_s8_kernel(const int8_t* __restrict__ Ah, const int8_t* __restrict__ Al,
             const float* __restrict__ sA,
             const int8_t* __restrict__ Bh, const int8_t* __restrict__ Bl,
             const float* __restrict__ sB,
             float* __restrict__ C, const float* __restrict__ AUX,
             const int8_t* __restrict__ AXh, const int8_t* __restrict__ AXl,
             const float* __restrict__ sAX,
             int K, int lda, int ldb, int ldc, int ldaux,
             int divA, long strA1, long strA2,
             int divB, long strB1, long strB2,
             int divC, long strC1, long strC2,
             long sAux) {
    extern __shared__ char smem[];
    const uint32_t sb = smem_to_u32(smem);
    const int tid = threadIdx.x;
    const int wid = tid >> 5;
    const int lane = tid & 31;
    const int wr = wid >> 2;
    const int wc = wid & 3;
    const int g = lane >> 2;
    const int tig = lane & 3;

    const int z = blockIdx.z;
    const long offA = (long)(z / divA) * strA1 + (long)(z % divA) * strA2;
    const long offB = (long)(z / divB) * strB1 + (long)(z % divB) * strB2;
    Ah += offA; Al += offA; Bh += offB; Bl += offB;
    C += (long)(z / divC) * strC1 + (long)(z % divC) * strC2;
    if (EPI == 2) AUX += (long)z * sAux;
    if (EPI == 3) { AXh += (long)z * sAux; AXl += (long)z * sAux; sAX += (long)z * (sAux / ldaux); }
    const long sAoff = (long)(z / divA) * (strA1 / lda) + (long)(z % divA) * (strA2 / lda);
    const long sBoff = (long)(z / divB) * (strB1 / ldb) + (long)(z % divB) * (strB2 / ldb);
    const int rowBase = blockIdx.y * 128;
    const int colBase = blockIdx.x * 128;

    int acc1[4][4][4], acc2[4][4][4];
    #pragma unroll
    for (int i = 0; i < 4; i++)
        #pragma unroll
        for (int j = 0; j < 4; j++)
            #pragma unroll
            for (int k = 0; k < 4; k++) { acc1[i][j][k] = 0; acc2[i][j][k] = 0; }

    const int nStages = K >> 6;

    auto stage = [&](int buf, int c) {
        const int k0 = c << 6;
        #pragma unroll
        for (int i = 0; i < 2; i++) {
            int ch = tid + 256 * i;
            int row = ch >> 2;
            int grp = ch & 3;
            uint32_t dst = (uint32_t)(row * 64 + 16 * (grp ^ ((row >> 1) & 3)));
            long srcA = (long)(rowBase + row) * lda + k0 + grp * 16;
            long srcB = (long)(colBase + row) * ldb + k0 + grp * 16;
            cp16(tile_addr(sb, buf, 0) + dst, Ah + srcA);
            cp16(tile_addr(sb, buf, 1) + dst, Al + srcA);
            cp16(tile_addr(sb, buf, 2) + dst, Bh + srcB);
            cp16(tile_addr(sb, buf, 3) + dst, Bl + srcB);
        }
    };

    auto compute = [&](int buf) {
        #pragma unroll
        for (int s = 0; s < 2; s++) {
            uint32_t afr[2][4][4], bfr[2][4][2];
            #pragma unroll
            for (int hl = 0; hl < 2; hl++) {
                const uint32_t tb = tile_addr(sb, buf, hl);
                const int row0 = wr * 64 + (lane & 7) + 8 * ((lane >> 3) & 1);
                const int grp = 2 * s + (lane >> 4);
                #pragma unroll
                for (int ms = 0; ms < 4; ms++) {
                    int row = row0 + ms * 16;
                    ldsm_x4(&afr[hl][ms][0],
                            tb + (uint32_t)(row * 64 + 16 * (grp ^ ((row >> 1) & 3))));
                }
            }
            #pragma unroll
            for (int hl = 0; hl < 2; hl++) {
                const uint32_t tb = tile_addr(sb, buf, 2 + hl);
                const int nrow0 = wc * 32 + (lane & 7) + 8 * (lane >> 4);
                const int grp = 2 * s + ((lane >> 3) & 1);
                #pragma unroll
                for (int p = 0; p < 2; p++) {
                    int nrow = nrow0 + p * 16;
                    uint32_t r4[4];
                    ldsm_x4(r4, tb + (uint32_t)(nrow * 64 + 16 * (grp ^ ((nrow >> 1) & 3))));
                    bfr[hl][2 * p][0] = r4[0]; bfr[hl][2 * p][1] = r4[1];
                    bfr[hl][2 * p + 1][0] = r4[2]; bfr[hl][2 * p + 1][1] = r4[3];
                }
            }
            #pragma unroll
            for (int ms = 0; ms < 4; ms++)
                #pragma unroll
                for (int ns = 0; ns < 4; ns++)
                    mma_s8(acc1[ms][ns], afr[0][ms], bfr[0][ns]);
            #pragma unroll
            for (int ms = 0; ms < 4; ms++)
                #pragma unroll
                for (int ns = 0; ns < 4; ns++)
                    mma_s8(acc2[ms][ns], afr[0][ms], bfr[1][ns]);
            #pragma unroll
            for (int ms = 0; ms < 4; ms++)
                #pragma unroll
                for (int ns = 0; ns < 4; ns++)
                    mma_s8(acc2[ms][ns], afr[1][ms], bfr[0][ns]);
        }
    };

    stage(0, 0); CP_COMMIT();
    if (nStages > 1) { stage(1, 1); CP_COMMIT(); }
    if (nStages > 2) { stage(2, 2); CP_COMMIT(); }
    int buf = 0;
    for (int c = 0; c < nStages; c++) {
        if (c + 2 < nStages) { CP_WAIT2(); }
        else if (c + 1 < nStages) { CP_WAIT1(); }
        else { CP_WAIT0(); }
        __syncthreads();
        compute(buf);
        if (c + 3 < nStages) {
            int nb = buf + 3; if (nb >= NBUF) nb -= NBUF;
            stage(nb, c + 3);
            CP_COMMIT();
        }
        if (++buf == NBUF) buf = 0;
    }

    #pragma unroll
    for (int ms = 0; ms < 4; ms++) {
        const int r = rowBase + wr * 64 + ms * 16 + g;
        const float sr0 = sA[sAoff + r];
        const float sr1 = sA[sAoff + r + 8];
        float xs0 = 0.0f, xs1 = 0.0f;
        if (EPI == 3) { xs0 = sAX[r]; xs1 = sAX[r + 8]; }
        #pragma unroll
        for (int ns = 0; ns < 4; ns++) {
            const int col = colBase + wc * 32 + ns * 8 + tig * 2;
            const float sc0 = sB[sBoff + col];
            const float sc1 = sB[sBoff + col + 1];
            float2 v0, v1;
            v0.x = sr0 * sc0 * ((float)acc1[ms][ns][0] + (float)acc2[ms][ns][0] * 0.00390625f);
            v0.y = sr0 * sc1 * ((float)acc1[ms][ns][1] + (float)acc2[ms][ns][1] * 0.00390625f);
            v1.x = sr1 * sc0 * ((float)acc1[ms][ns][2] + (float)acc2[ms][ns][2] * 0.00390625f);
            v1.y = sr1 * sc1 * ((float)acc1[ms][ns][3] + (float)acc2[ms][ns][3] * 0.00390625f);
            if (EPI >= 1) {
                v0.x = fmaxf(v0.x, 0.0f); v0.y = fmaxf(v0.y, 0.0f);
                v1.x = fmaxf(v1.x, 0.0f); v1.y = fmaxf(v1.y, 0.0f);
            }
            if (EPI == 2) {
                float2 a0 = *(const float2*)(AUX + (long)r * ldaux + col);
                float2 a1 = *(const float2*)(AUX + (long)(r + 8) * ldaux + col);
                v0.x *= a0.x; v0.y *= a0.y;
                v1.x *= a1.x; v1.y *= a1.y;
            }
            if (EPI == 3) {
                char2 h0 = *(const char2*)(AXh + (long)r * ldaux + col);
                char2 l0 = *(const char2*)(AXl + (long)r * ldaux + col);
                char2 h1 = *(const char2*)(AXh + (long)(r + 8) * ldaux + col);
                char2 l1 = *(const char2*)(AXl + (long)(r + 8) * ldaux + col);
                v0.x *= xs0 * ((float)h0.x + (float)l0.x * 0.00390625f);
                v0.y *= xs0 * ((float)h0.y + (float)l0.y * 0.00390625f);
                v1.x *= xs1 * ((float)h1.x + (float)l1.x * 0.00390625f);
                v1.y *= xs1 * ((float)h1.y + (float)l1.y * 0.00390625f);
            }
            *(float2*)(C + (long)r * ldc + col) = v0;
            *(float2*)(C + (long)(r + 8) * ldc + col) = v1;
        }
    }
}

// ---------------------------------------------------------------------------
// Reductions
// ---------------------------------------------------------------------------
__device__ __forceinline__ float block_sum_256(float v, float* smem) {
    #pragma unroll
    for (int o = 16; o > 0; o >>= 1) v += __shfl_down_sync(0xffffffffu, v, o);
    int w = threadIdx.x >> 5, l = threadIdx.x & 31;
    if (l == 0) smem[w] = v;
    __syncthreads();
    if (w == 0) {
        float s = (l < 8) ? smem[l] : 0.0f;
        #pragma unroll
        for (int o = 4; o > 0; o >>= 1) s += __shfl_down_sync(0xffffffffu, s, o);
        if (l == 0) smem[0] = s;
    }
    __syncthreads();
    float r = smem[0];
    __syncthreads();
    return r;
}
__device__ __forceinline__ float block_max_256(float v, float* smem) {
    #pragma unroll
    for (int o = 16; o > 0; o >>= 1) v = fmaxf(v, __shfl_down_sync(0xffffffffu, v, o));
    int w = threadIdx.x >> 5, l = threadIdx.x & 31;
    if (l == 0) smem[w] = v;
    __syncthreads();
    if (w == 0) {
        float s = (l < 8) ? smem[l] : 0.0f;
        #pragma unroll
        for (int o = 4; o > 0; o >>= 1) s = fmaxf(s, __shfl_down_sync(0xffffffffu, s, o));
        if (l == 0) smem[0] = s;
    }
    __syncthreads();
    float r = smem[0];
    __syncthreads();
    return r;
}

// ---------------------------------------------------------------------------
// Quantization kernels
// ---------------------------------------------------------------------------
__global__ void qrow_kernel(const float* __restrict__ in,
                            int8_t* __restrict__ oh, int8_t* __restrict__ ol,
                            float* __restrict__ os, int K) {
    extern __shared__ float stash[];
    __shared__ float red[8];
    long row = blockIdx.x;
    const float4* p = (const float4*)(in + row * K);
    int n4 = K >> 2;
    float m = 0.0f;
    for (int i = threadIdx.x; i < n4; i += 256) {
        float4 v = p[i];
        ((float4*)stash)[i] = v;
        m = fmaxf(m, fmaxf(fmaxf(fabsf(v.x), fabsf(v.y)), fmaxf(fabsf(v.z), fabsf(v.w))));
    }
    float s = block_max_256(m, red);
    if (threadIdx.x == 0) os[row] = s * (1.0f / 127.0f);
    float inv = (s > 0.0f) ? 127.0f / s : 0.0f;
    for (int i = threadIdx.x; i < n4; i += 256) {
        float4 v = ((float4*)stash)[i];
        int h0, l0, h1, l1, h2, l2, h3, l3;
        quant2(v.x * inv, h0, l0); quant2(v.y * inv, h1, l1);
        quant2(v.z * inv, h2, l2); quant2(v.w * inv, h3, l3);
        ((char4*)(oh + row * K))[i] = make_char4((char)h0, (char)h1, (char)h2, (char)h3);
        ((char4*)(ol + row * K))[i] = make_char4((char)l0, (char)l1, (char)l2, (char)l3);
    }
}

// Fill transposed-plane scales: sT[plane*cols + c] = max_r s[plane*R + r]
__global__ void fill_scaleT_kernel(const float* __restrict__ s, float* __restrict__ sT,
                                   int R, int cols) {
    __shared__ float red[8];
    long plane = blockIdx.x;
    float m = 0.0f;
    for (int r = threadIdx.x; r < R; r += 256) m = fmaxf(m, s[plane * R + r]);
    float mx = block_max_256(m, red);
    for (int c = threadIdx.x; c < cols; c += 256) sT[plane * cols + c] = mx;
}

// Transpose+requant from int8 h/l (per-row scales) -> int8 h/l (plane scale in sTarr).
__global__ void transquant_q_kernel(const int8_t* __restrict__ ih, const int8_t* __restrict__ il,
                                    const float* __restrict__ s, const float* __restrict__ sTarr,
                                    int8_t* __restrict__ oh, int8_t* __restrict__ ol,
                                    int rows, int cols) {
    __shared__ float t[32][33];
    long plane = blockIdx.z;
    int c0 = blockIdx.x * 32, r0 = blockIdx.y * 32;
    const int8_t* ph = ih + plane * (long)rows * cols;
    const int8_t* pl = il + plane * (long)rows * cols;
    int lr = threadIdx.x >> 5, lc = threadIdx.x & 31;
    #pragma unroll
    for (int j = 0; j < 4; j++) {
        int r = r0 + lr + j * 8;
        float sr = s[plane * rows + r];
        long idx = (long)r * cols + c0 + lc;
        t[lr + j * 8][lc] = sr * ((float)ph[idx] + (float)pl[idx] * 0.00390625f);
    }
    __syncthreads();
    float sp = sTarr[plane * cols + c0];
    float inv = (sp > 0.0f) ? 1.0f / sp : 0.0f;
    int orow = threadIdx.x >> 3, og = threadIdx.x & 7;
    int c = c0 + orow;
    char hv[4], lv[4];
    #pragma unroll
    for (int j = 0; j < 4; j++) {
        int h, l;
        quant2(t[og * 4 + j][orow] * inv, h, l);
        hv[j] = (char)h; lv[j] = (char)l;
    }
    long o = plane * (long)rows * cols + (long)c * rows + r0 + og * 4;
    *(char4*)(oh + o) = make_char4(hv[0], hv[1], hv[2], hv[3]);
    *(char4*)(ol + o) = make_char4(lv[0], lv[1], lv[2], lv[3]);
}

// Weight transpose+quant (one-time)
__global__ void wtq_kernel(const float* __restrict__ in,
                           int8_t* __restrict__ oh, int8_t* __restrict__ ol,
                           float* __restrict__ os, int Kin, int Nout) {
    extern __shared__ float stash[];
    __shared__ float red[8];
    long plane = blockIdx.y;
    int n = blockIdx.x;
    const float* p = in + plane * (long)Kin * Nout;
    float m = 0.0f;
    for (int k = threadIdx.x; k < Kin; k += 256) {
        float x = p[(long)k * Nout + n];
        stash[k] = x;
        m = fmaxf(m, fabsf(x));
    }
    float s = block_max_256(m, red);
    if (threadIdx.x == 0) os[plane * Nout + n] = s * (1.0f / 127.0f);
    float inv = (s > 0.0f) ? 127.0f / s : 0.0f;
    long o = plane * (long)Nout * Kin + (long)n * Kin;
    for (int k = threadIdx.x; k < Kin; k += 256) {
        int h, l;
        quant2(stash[k] * inv, h, l);
        oh[o + k] = (int8_t)h; ol[o + k] = (int8_t)l;
    }
}

// ---------------------------------------------------------------------------
// Elementwise kernels
// ---------------------------------------------------------------------------
__global__ void rope_tables_kernel(float* cosT, float* sinT) {
    int t = blockIdx.x, j = threadIdx.x;
    double inv = pow(10000.0, -(2.0 * (double)j) / (double)DH);
    double phase = (double)t * inv;
    float c = (float)cos(phase), s = (float)sin(phase);
    cosT[t * DH + j] = c;  cosT[t * DH + 512 + j] = c;
    sinT[t * DH + j] = s;  sinT[t * DH + 512 + j] = s;
}

// RoPE + row-quant of xr, PLUS row-quant of x itself (for GEMM5 AUX).
__global__ void rope_rowquant_kernel(const float* __restrict__ x,
                                     const float* __restrict__ cosT,
                                     const float* __restrict__ sinT,
                                     int8_t* __restrict__ qh, int8_t* __restrict__ ql,
                                     float* __restrict__ qs,
                                     int8_t* __restrict__ qxh, int8_t* __restrict__ qxl,
                                     float* __restrict__ qxs) {
    __shared__ float red[8];
    long bht = blockIdx.x;
    int t = (int)(bht & (TT - 1));
    const float* xp = x + bht * DH;
    float vals[4], xvals[4];
    float m = 0.0f, mx = 0.0f;
    #pragma unroll
    for (int j = 0; j < 4; j++) {
        int e = threadIdx.x + j * 256;
        float xv = xp[e];
        float ov = (e < 512) ? -xp[e + 512] : xp[e - 512];
        float r = xv * cosT[t * DH + e] + ov * sinT[t * DH + e];
        vals[j] = r;
        xvals[j] = xv;
        m = fmaxf(m, fabsf(r));
        mx = fmaxf(mx, fabsf(xv));
    }
    float s = block_max_256(m, red);
    float sx = block_max_256(mx, red);
    if (threadIdx.x == 0) {
        qs[bht] = s * (1.0f / 127.0f);
        qxs[bht] = sx * (1.0f / 127.0f);
    }
    float inv = (s > 0.0f) ? 127.0f / s : 0.0f;
    float invx = (sx > 0.0f) ? 127.0f / sx : 0.0f;
    #pragma unroll
    for (int j = 0; j < 4; j++) {
        int e = threadIdx.x + j * 256;
        int h, l;
        quant2(vals[j] * inv, h, l);
        qh[bht * DH + e] = (int8_t)h;
        ql[bht * DH + e] = (int8_t)l;
        quant2(xvals[j] * invx, h, l);
        qxh[bht * DH + e] = (int8_t)h;
        qxl[bht * DH + e] = (int8_t)l;
    }
}

__global__ void embed_ln_kernel(const int* __restrict__ tokens,
                                const float* __restrict__ emb_w,
                                float* __restrict__ v,
                                int8_t* __restrict__ qh, int8_t* __restrict__ ql,
                                float* __restrict__ qs) {
    __shared__ float smem[8];
    int bt = blockIdx.x, d = threadIdx.x;
    float val = emb_w[tokens[bt] * DD + d];
    float m = block_sum_256(val, smem) * (1.0f / DD);
    float c = val - m;
    float var = block_sum_256(c * c, smem) * (1.0f / DD);
    float r = c * rsqrtf(var + EPS);
    long i = (long)bt * DD + d;
    v[i] = r;
    float s = block_max_256(fabsf(r), smem);
    if (d == 0) qs[bt] = s * (1.0f / 127.0f);
    float inv = (s > 0.0f) ? 127.0f / s : 0.0f;
    int h, l;
    quant2(r * inv, h, l);
    qh[i] = (int8_t)h; ql[i] = (int8_t)l;
}

// v = LN(v + LN(z0+z1+z2+z3)); also emits row-quant of v.
__global__ void fuse_ln4_kernel(const float* __restrict__ z,
                                float* __restrict__ v,
                                int8_t* __restrict__ qh, int8_t* __restrict__ ql,
                                float* __restrict__ qs) {
    __shared__ float smem[8];
    int bt = blockIdx.x, d = threadIdx.x;
    long i = (long)bt * DD + d;
    const long S = (long)BB * TT * DD;
    float u = z[i] + z[i + S] + z[i + 2 * S] + z[i + 3 * S];
    float m1 = block_sum_256(u, smem) * (1.0f / DD);
    float c1 = u - m1;
    float var1 = block_sum_256(c1 * c1, smem) * (1.0f / DD);
    float lnz = c1 * rsqrtf(var1 + EPS);
    float w = v[i] + lnz;
    float m2 = block_sum_256(w, smem) * (1.0f / DD);
    float c2 = w - m2;
    float var2 = block_sum_256(c2 * c2, smem) * (1.0f / DD);
    float r = c2 * rsqrtf(var2 + EPS);
    v[i] = r;
    float s = block_max_256(fabsf(r), smem);
    if (d == 0) qs[bt] = s * (1.0f / 127.0f);
    float inv = (s > 0.0f) ? 127.0f / s : 0.0f;
    int h, l;
    quant2(r * inv, h, l);
    qh[i] = (int8_t)h; ql[i] = (int8_t)l;
}

// ---------------------------------------------------------------------------
// Host launcher
// ---------------------------------------------------------------------------
#define GET(sym, var) cudaGetSymbolAddress((void**)&var, sym)

extern "C" void kernel_launch(void* const* d_in, const int* in_sizes, int n_in,
                              void* d_out, int out_size) {
    const int*   tokens  = (const int*)d_in[0];
    const float* emb_w   = (const float*)d_in[1];
    const float* E       = (const float*)d_in[2];
    const float* Dx      = (const float*)d_in[3];
    const float* Dy      = (const float*)d_in[4];
    const float* readout = (const float*)d_in[5];
    float* out = (float*)d_out;

    float *v, *x, *w2, *a, *ye, *zb, *cosT, *sinT;
    GET(g_v, v); GET(g_x, x); GET(g_w2, w2); GET(g_a, a);
    GET(g_ye, ye); GET(g_z, zb); GET(g_cos, cosT); GET(g_sin, sinT);

    int8_t *vqh, *vql, *vTh, *vTl, *qxh, *qxl, *xrh, *xrl, *xrTh, *xrTl, *w2h, *w2l;
    int8_t *ah, *al, *yeh, *yel, *dxh, *dxl, *dyh, *dyl, *eh, *el, *roh, *rol;
    GET(q_v_h, vqh); GET(q_v_l, vql); GET(q_vT_h, vTh); GET(q_vT_l, vTl);
    GET(q_x_h, qxh); GET(q_x_l, qxl);
    GET(q_xr_h, xrh); GET(q_xr_l, xrl); GET(q_xrT_h, xrTh); GET(q_xrT_l, xrTl);
    GET(q_w2_h, w2h); GET(q_w2_l, w2l); GET(q_a_h, ah); GET(q_a_l, al);
    GET(q_ye_h, yeh); GET(q_ye_l, yel);
    GET(q_dxT_h, dxh); GET(q_dxT_l, dxl); GET(q_dyT_h, dyh); GET(q_dyT_l, dyl);
    GET(q_eT_h, eh); GET(q_eT_l, el); GET(q_roT_h, roh); GET(q_roT_l, rol);

    float *sv, *svT, *sx, *sxr, *sxrT, *sw2, *sa, *sye, *sdx, *sdy, *se, *sro;
    GET(sc_v, sv); GET(sc_vT, svT); GET(sc_x, sx); GET(sc_xr, sxr); GET(sc_xrT, sxrT);
    GET(sc_w2, sw2); GET(sc_a, sa); GET(sc_ye, sye);
    GET(sc_dx, sdx); GET(sc_dy, sdy); GET(sc_e, se); GET(sc_ro, sro);

    cudaFuncSetAttribute(mm_s8_kernel<0>, cudaFuncAttributeMaxDynamicSharedMemorySize, SMEM_SZ);
    cudaFuncSetAttribute(mm_s8_kernel<1>, cudaFuncAttributeMaxDynamicSharedMemorySize, SMEM_SZ);
    cudaFuncSetAttribute(mm_s8_kernel<3>, cudaFuncAttributeMaxDynamicSharedMemorySize, SMEM_SZ);

    rope_tables_kernel<<<TT, 512>>>(cosT, sinT);
    embed_ln_kernel<<<BB * TT, 256>>>(tokens, emb_w, v, vqh, vql, sv);

    // Weight prep (once)
    wtq_kernel<<<dim3(DH, HH), 256, DD * 4>>>(Dx, dxh, dxl, sdx, DD, DH);
    wtq_kernel<<<dim3(DH, HH), 256, DD * 4>>>(Dy, dyh, dyl, sdy, DD, DH);
    wtq_kernel<<<dim3(DD, 1), 256, NN_ * 4>>>(E, eh, el, se, NN_, DD);
    wtq_kernel<<<dim3(VV, 1), 256, DD * 4>>>(readout, roh, rol, sro, DD, VV);

    const long TDh = (long)TT * DH;
    const long TD  = (long)TT * DD;
    const long DDh = (long)DD * DH;
    const long TN  = (long)TT * NN_;

    // vT quant for layer 0
    fill_scaleT_kernel<<<BB, 256>>>(sv, svT, TT, DD);
    transquant_q_kernel<<<dim3(DD / 32, TT / 32, BB), 256>>>(vqh, vql, sv, svT, vTh, vTl, TT, DD);

    for (int l = 0; l < LL; l++) {
        // 1) x = relu(v @ DxT^T): M=T N=Dh K=D  (fp32 out for rope)
        mm_s8_kernel<1><<<dim3(8, 8, BB * HH), 256, SMEM_SZ>>>(
            vqh, vql, sv, dxh, dxl, sdx, x, nullptr, nullptr, nullptr, nullptr,
            DD, DD, DD, DH, 0,
            HH, TD, 0,   HH, 0, DDh,   1, TDh, 0,   0);

        // 2) RoPE + rowquant of xr AND x
        rope_rowquant_kernel<<<BB * HH * TT, 256>>>(x, cosT, sinT,
                                                    xrh, xrl, sxr, qxh, qxl, sx);
        fill_scaleT_kernel<<<BB * HH, 256>>>(sxr, sxrT, TT, DH);
        transquant_q_kernel<<<dim3(DH / 32, TT / 32, BB * HH), 256>>>(
            xrh, xrl, sxr, sxrT, xrTh, xrTl, TT, DH);

        // 3) w2 = vT @ xrT^T: M=D N=Dh K=T
        mm_s8_kernel<0><<<dim3(8, 2, BB * HH), 256, SMEM_SZ>>>(
            vTh, vTl, svT, xrTh, xrTl, sxrT, w2, nullptr, nullptr, nullptr, nullptr,
            TT, TT, TT, DH, 0,
            HH, (long)DD * TT, 0,   1, (long)DH * TT, 0,   1, DDh, 0,   0);
        qrow_kernel<<<BB * HH * DD, 256, DH * 4>>>(w2, w2h, w2l, sw2, DH);

        // 4) a = xr @ w2^T: M=T N=D K=Dh
        mm_s8_kernel<0><<<dim3(2, 8, BB * HH), 256, SMEM_SZ>>>(
            xrh, xrl, sxr, w2h, w2l, sw2, a, nullptr, nullptr, nullptr, nullptr,
            DH, DH, DH, DD, 0,
            1, TDh, 0,   1, DDh, 0,   1, TD, 0,   0);
        qrow_kernel<<<BB * HH * TT, 256, DD * 4>>>(a, ah, al, sa, DD);

        // 5) ye = relu(a @ DyT^T) * x: M=T N=Dh K=D — AUX as int8 h/l (EPI=3)
        mm_s8_kernel<3><<<dim3(8, 8, BB * HH), 256, SMEM_SZ>>>(
            ah, al, sa, dyh, dyl, sdy, ye, nullptr, qxh, qxl, sx,
            DD, DD, DD, NN_, DH,
            1, TD, 0,   HH, 0, DDh,   HH, TN, DH,   TDh);
        qrow_kernel<<<BB * TT, 256, NN_ * 4>>>(ye, yeh, yel, sye, NN_);

        // 6) z partials (split-K x4): M=B*T N=D K=1024 each
        mm_s8_kernel<0><<<dim3(2, 32, 4), 256, SMEM_SZ>>>(
            yeh, yel, sye, eh, el, se, zb, nullptr, nullptr, nullptr, nullptr,
            NN_ / 4, NN_, NN_, DD, 0,
            1, NN_ / 4, 0,   1, NN_ / 4, 0,   1, (long)BB * TT * DD, 0,   0);

        // 7) v = LN(v + LN(sum z)) + rowquant; vT requant
        fuse_ln4_kernel<<<BB * TT, 256>>>(zb, v, vqh, vql, sv);
        fill_scaleT_kernel<<<BB, 256>>>(sv, svT, TT, DD);
        transquant_q_kernel<<<dim3(DD / 32, TT / 32, BB), 256>>>(
            vqh, vql, sv, svT, vTh, vTl, TT, DD);
    }

    // out = v @ roT^T: M=B*T N=V K=D
    mm_s8_kernel<0><<<dim3(2, 32, 1), 256, SMEM_SZ>>>(
        vqh, vql, sv, roh, rol, sro, out, nullptr, nullptr, nullptr, nullptr,
        DD, DD, DD, VV, 0,
        1, 0, 0,   1, 0, 0,   1, 0, 0,   0);
}

// round 14
// speedup vs baseline: 1.0668x; 1.0668x over previous
#include <cuda_runtime.h>
#include <cuda_bf16.h>
#include <math.h>
#include <stdint.h>

#define BB 4
#define TT 1024
#define HH 4
#define NN_ 4096
#define DD 256
#define DH 1024
#define LL 6
#define VV 256
#define EPS 1e-5f

// ---------------------------------------------------------------------------
// Scratch (device globals)
// ---------------------------------------------------------------------------
__device__ float g_v[BB * TT * DD];
__device__ float g_x[BB * HH * TT * DH];
__device__ float g_w2[BB * HH * DD * DH];
__device__ float g_a[BB * HH * TT * DD];
__device__ float g_ye[BB * TT * NN_];
__device__ float g_z[2 * BB * TT * DD];
__device__ float g_cos[TT * DH];
__device__ float g_sin[TT * DH];

// int8 quantized operands (h, l) + per-row scales
__device__ int8_t q_v_h[BB * TT * DD],      q_v_l[BB * TT * DD];
__device__ int8_t q_vT_h[BB * DD * TT],     q_vT_l[BB * DD * TT];
__device__ int8_t q_xr_h[BB * HH * TT * DH], q_xr_l[BB * HH * TT * DH];
__device__ int8_t q_xrT_h[BB * HH * DH * TT], q_xrT_l[BB * HH * DH * TT];
__device__ int8_t q_w2_h[BB * HH * DD * DH], q_w2_l[BB * HH * DD * DH];
__device__ int8_t q_a_h[BB * HH * TT * DD],  q_a_l[BB * HH * TT * DD];
__device__ int8_t q_ye_h[BB * TT * NN_],     q_ye_l[BB * TT * NN_];
__device__ int8_t q_dxT_h[HH * DH * DD],     q_dxT_l[HH * DH * DD];
__device__ int8_t q_dyT_h[HH * DH * DD],     q_dyT_l[HH * DH * DD];
__device__ int8_t q_eT_h[DD * NN_],          q_eT_l[DD * NN_];
__device__ int8_t q_roT_h[VV * DD],          q_roT_l[VV * DD];

__device__ float sc_v[BB * TT];
__device__ float sc_vT[BB * DD];
__device__ float sc_xr[BB * HH * TT];
__device__ float sc_xrT[BB * HH * DH];
__device__ float sc_w2[BB * HH * DD];
__device__ float sc_a[BB * HH * TT];
__device__ float sc_ye[BB * TT];
__device__ float sc_dx[HH * DH];
__device__ float sc_dy[HH * DH];
__device__ float sc_e[DD];
__device__ float sc_ro[VV];

// ---------------------------------------------------------------------------
// PTX helpers
// ---------------------------------------------------------------------------
__device__ __forceinline__ uint32_t smem_to_u32(const void* p) {
    uint32_t a;
    asm("{ .reg .u64 t; cvta.to.shared.u64 t, %1; cvt.u32.u64 %0, t; }" : "=r"(a) : "l"(p));
    return a;
}
__device__ __forceinline__ void cp16(uint32_t dst, const void* src) {
    asm volatile("cp.async.cg.shared.global [%0], [%1], 16;" :: "r"(dst), "l"(src));
}
#define CP_COMMIT() asm volatile("cp.async.commit_group;" ::: "memory")
#define CP_WAIT0() asm volatile("cp.async.wait_group 0;" ::: "memory")
#define CP_WAIT1() asm volatile("cp.async.wait_group 1;" ::: "memory")
#define CP_WAIT2() asm volatile("cp.async.wait_group 2;" ::: "memory")

__device__ __forceinline__ void ldsm_x4(uint32_t* r, uint32_t addr) {
    asm volatile("ldmatrix.sync.aligned.m8n8.x4.shared.b16 {%0,%1,%2,%3}, [%4];"
                 : "=r"(r[0]), "=r"(r[1]), "=r"(r[2]), "=r"(r[3]) : "r"(addr));
}
__device__ __forceinline__ void mma_s8(int* d, const uint32_t* a, const uint32_t* b) {
    asm volatile(
        "mma.sync.aligned.m16n8k32.row.col.s32.s8.s8.s32 "
        "{%0,%1,%2,%3}, {%4,%5,%6,%7}, {%8,%9}, {%0,%1,%2,%3};"
        : "+r"(d[0]), "+r"(d[1]), "+r"(d[2]), "+r"(d[3])
        : "r"(a[0]), "r"(a[1]), "r"(a[2]), "r"(a[3]), "r"(b[0]), "r"(b[1]));
}

__device__ __forceinline__ void quant2(float u, int& h, int& l) {
    h = __float2int_rn(u);
    if (h > 127) h = 127; else if (h < -127) h = -127;
    l = __float2int_rn((u - (float)h) * 256.0f);
    if (l > 127) l = 127; else if (l < -127) l = -127;
}

// ---------------------------------------------------------------------------
// int8 two-level GEMM: C = epi(sA*sB*(A@B^T)), 128x128 CTA tile, 8 warps.
// EPI 0: acc; 1: relu; 2: relu*AUX.
// ---------------------------------------------------------------------------
#define TILE_B 8192
#define NBUF 4
#define SMEM_SZ (NBUF * 4 * TILE_B)
__device__ __forceinline__ uint32_t tile_addr(uint32_t sb, int buf, int which) {
    return sb + (uint32_t)((buf * 4 + which) * TILE_B);
}

template <int EPI>
__global__ void __launch_bounds__(256)
mm_s8_kernel(const int8_t* __restrict__ Ah, const int8_t* __restrict__ Al,
             const float* __restrict__ sA,
             const int8_t* __restrict__ Bh, const int8_t* __restrict__ Bl,
             const float* __restrict__ sB,
             float* __restrict__ C, const float* __restrict__ AUX,
             int K, int lda, int ldb, int ldc, int ldaux,
             int divA, long strA1, long strA2,
             int divB, long strB1, long strB2,
             int divC, long strC1, long strC2,
             long sAux) {
    extern __shared__ char smem[];
    const uint32_t sb = smem_to_u32(smem);
    const int tid = threadIdx.x;
    const int wid = tid >> 5;
    const int lane = tid & 31;
    const int wr = wid >> 2;
    const int wc = wid & 3;
    const int g = lane >> 2;
    const int tig = lane & 3;

    const int z = blockIdx.z;
    const long offA = (long)(z / divA) * strA1 + (long)(z % divA) * strA2;
    const long offB = (long)(z / divB) * strB1 + (long)(z % divB) * strB2;
    Ah += offA; Al += offA; Bh += offB; Bl += offB;
    C += (long)(z / divC) * strC1 + (long)(z % divC) * strC2;
    if (EPI == 2) AUX += (long)z * sAux;
    const long sAoff = (long)(z / divA) * (strA1 / lda) + (long)(z % divA) * (strA2 / lda);
    const long sBoff = (long)(z / divB) * (strB1 / ldb) + (long)(z % divB) * (strB2 / ldb);
    const int rowBase = blockIdx.y * 128;
    const int colBase = blockIdx.x * 128;

    int acc1[4][4][4], acc2[4][4][4];
    #pragma unroll
    for (int i = 0; i < 4; i++)
        #pragma unroll
        for (int j = 0; j < 4; j++)
            #pragma unroll
            for (int k = 0; k < 4; k++) { acc1[i][j][k] = 0; acc2[i][j][k] = 0; }

    const int nStages = K >> 6;

    auto stage = [&](int buf, int c) {
        const int k0 = c << 6;
        #pragma unroll
        for (int i = 0; i < 2; i++) {
            int ch = tid + 256 * i;
            int row = ch >> 2;
            int grp = ch & 3;
            uint32_t dst = (uint32_t)(row * 64 + 16 * (grp ^ ((row >> 1) & 3)));
            long srcA = (long)(rowBase + row) * lda + k0 + grp * 16;
            long srcB = (long)(colBase + row) * ldb + k0 + grp * 16;
            cp16(tile_addr(sb, buf, 0) + dst, Ah + srcA);
            cp16(tile_addr(sb, buf, 1) + dst, Al + srcA);
            cp16(tile_addr(sb, buf, 2) + dst, Bh + srcB);
            cp16(tile_addr(sb, buf, 3) + dst, Bl + srcB);
        }
    };

    auto compute = [&](int buf) {
        #pragma unroll
        for (int s = 0; s < 2; s++) {
            uint32_t afr[2][4][4], bfr[2][4][2];
            #pragma unroll
            for (int hl = 0; hl < 2; hl++) {
                const uint32_t tb = tile_addr(sb, buf, hl);
                const int row0 = wr * 64 + (lane & 7) + 8 * ((lane >> 3) & 1);
                const int grp = 2 * s + (lane >> 4);
                #pragma unroll
                for (int ms = 0; ms < 4; ms++) {
                    int row = row0 + ms * 16;
                    ldsm_x4(&afr[hl][ms][0],
                            tb + (uint32_t)(row * 64 + 16 * (grp ^ ((row >> 1) & 3))));
                }
            }
            #pragma unroll
            for (int hl = 0; hl < 2; hl++) {
                const uint32_t tb = tile_addr(sb, buf, 2 + hl);
                const int nrow0 = wc * 32 + (lane & 7) + 8 * (lane >> 4);
                const int grp = 2 * s + ((lane >> 3) & 1);
                #pragma unroll
                for (int p = 0; p < 2; p++) {
                    int nrow = nrow0 + p * 16;
                    uint32_t r4[4];
                    ldsm_x4(r4, tb + (uint32_t)(nrow * 64 + 16 * (grp ^ ((nrow >> 1) & 3))));
                    bfr[hl][2 * p][0] = r4[0]; bfr[hl][2 * p][1] = r4[1];
                    bfr[hl][2 * p + 1][0] = r4[2]; bfr[hl][2 * p + 1][1] = r4[3];
                }
            }
            #pragma unroll
            for (int ms = 0; ms < 4; ms++)
                #pragma unroll
                for (int ns = 0; ns < 4; ns++)
                    mma_s8(acc1[ms][ns], afr[0][ms], bfr[0][ns]);
            #pragma unroll
            for (int ms = 0; ms < 4; ms++)
                #pragma unroll
                for (int ns = 0; ns < 4; ns++)
                    mma_s8(acc2[ms][ns], afr[0][ms], bfr[1][ns]);
            #pragma unroll
            for (int ms = 0; ms < 4; ms++)
                #pragma unroll
                for (int ns = 0; ns < 4; ns++)
                    mma_s8(acc2[ms][ns], afr[1][ms], bfr[0][ns]);
        }
    };

    stage(0, 0); CP_COMMIT();
    if (nStages > 1) { stage(1, 1); CP_COMMIT(); }
    if (nStages > 2) { stage(2, 2); CP_COMMIT(); }
    int buf = 0;
    for (int c = 0; c < nStages; c++) {
        if (c + 2 < nStages) { CP_WAIT2(); }
        else if (c + 1 < nStages) { CP_WAIT1(); }
        else { CP_WAIT0(); }
        __syncthreads();
        compute(buf);
        if (c + 3 < nStages) {
            int nb = buf + 3; if (nb >= NBUF) nb -= NBUF;
            stage(nb, c + 3);
            CP_COMMIT();
        }
        if (++buf == NBUF) buf = 0;
    }

    #pragma unroll
    for (int ms = 0; ms < 4; ms++) {
        const int r = rowBase + wr * 64 + ms * 16 + g;
        const float sr0 = sA[sAoff + r];
        const float sr1 = sA[sAoff + r + 8];
        #pragma unroll
        for (int ns = 0; ns < 4; ns++) {
            const int col = colBase + wc * 32 + ns * 8 + tig * 2;
            const float sc0 = sB[sBoff + col];
            const float sc1 = sB[sBoff + col + 1];
            float2 v0, v1;
            v0.x = sr0 * sc0 * ((float)acc1[ms][ns][0] + (float)acc2[ms][ns][0] * 0.00390625f);
            v0.y = sr0 * sc1 * ((float)acc1[ms][ns][1] + (float)acc2[ms][ns][1] * 0.00390625f);
            v1.x = sr1 * sc0 * ((float)acc1[ms][ns][2] + (float)acc2[ms][ns][2] * 0.00390625f);
            v1.y = sr1 * sc1 * ((float)acc1[ms][ns][3] + (float)acc2[ms][ns][3] * 0.00390625f);
            if (EPI >= 1) {
                v0.x = fmaxf(v0.x, 0.0f); v0.y = fmaxf(v0.y, 0.0f);
                v1.x = fmaxf(v1.x, 0.0f); v1.y = fmaxf(v1.y, 0.0f);
            }
            if (EPI == 2) {
                float2 a0 = *(const float2*)(AUX + (long)r * ldaux + col);
                float2 a1 = *(const float2*)(AUX + (long)(r + 8) * ldaux + col);
                v0.x *= a0.x; v0.y *= a0.y;
                v1.x *= a1.x; v1.y *= a1.y;
            }
            *(float2*)(C + (long)r * ldc + col) = v0;
            *(float2*)(C + (long)(r + 8) * ldc + col) = v1;
        }
    }
}

// ---------------------------------------------------------------------------
// Reductions
// ---------------------------------------------------------------------------
__device__ __forceinline__ float block_sum_256(float v, float* smem) {
    #pragma unroll
    for (int o = 16; o > 0; o >>= 1) v += __shfl_down_sync(0xffffffffu, v, o);
    int w = threadIdx.x >> 5, l = threadIdx.x & 31;
    if (l == 0) smem[w] = v;
    __syncthreads();
    if (w == 0) {
        float s = (l < 8) ? smem[l] : 0.0f;
        #pragma unroll
        for (int o = 4; o > 0; o >>= 1) s += __shfl_down_sync(0xffffffffu, s, o);
        if (l == 0) smem[0] = s;
    }
    __syncthreads();
    float r = smem[0];
    __syncthreads();
    return r;
}
__device__ __forceinline__ float block_max_256(float v, float* smem) {
    #pragma unroll
    for (int o = 16; o > 0; o >>= 1) v = fmaxf(v, __shfl_down_sync(0xffffffffu, v, o));
    int w = threadIdx.x >> 5, l = threadIdx.x & 31;
    if (l == 0) smem[w] = v;
    __syncthreads();
    if (w == 0) {
        float s = (l < 8) ? smem[l] : 0.0f;
        #pragma unroll
        for (int o = 4; o > 0; o >>= 1) s = fmaxf(s, __shfl_down_sync(0xffffffffu, s, o));
        if (l == 0) smem[0] = s;
    }
    __syncthreads();
    float r = smem[0];
    __syncthreads();
    return r;
}

// ---------------------------------------------------------------------------
// Quantization kernels
// ---------------------------------------------------------------------------
__global__ void qrow_kernel(const float* __restrict__ in,
                            int8_t* __restrict__ oh, int8_t* __restrict__ ol,
                            float* __restrict__ os, int K) {
    extern __shared__ float stash[];
    __shared__ float red[8];
    long row = blockIdx.x;
    const float4* p = (const float4*)(in + row * K);
    int n4 = K >> 2;
    float m = 0.0f;
    for (int i = threadIdx.x; i < n4; i += 256) {
        float4 v = p[i];
        ((float4*)stash)[i] = v;
        m = fmaxf(m, fmaxf(fmaxf(fabsf(v.x), fabsf(v.y)), fmaxf(fabsf(v.z), fabsf(v.w))));
    }
    float s = block_max_256(m, red);
    if (threadIdx.x == 0) os[row] = s * (1.0f / 127.0f);
    float inv = (s > 0.0f) ? 127.0f / s : 0.0f;
    for (int i = threadIdx.x; i < n4; i += 256) {
        float4 v = ((float4*)stash)[i];
        int h0, l0, h1, l1, h2, l2, h3, l3;
        quant2(v.x * inv, h0, l0); quant2(v.y * inv, h1, l1);
        quant2(v.z * inv, h2, l2); quant2(v.w * inv, h3, l3);
        ((char4*)(oh + row * K))[i] = make_char4((char)h0, (char)h1, (char)h2, (char)h3);
        ((char4*)(ol + row * K))[i] = make_char4((char)l0, (char)l1, (char)l2, (char)l3);
    }
}

// Fill transposed-plane scales: sT[plane*cols + c] = max_r s[plane*R + r]
__global__ void fill_scaleT_kernel(const float* __restrict__ s, float* __restrict__ sT,
                                   int R, int cols) {
    __shared__ float red[8];
    long plane = blockIdx.x;
    float m = 0.0f;
    for (int r = threadIdx.x; r < R; r += 256) m = fmaxf(m, s[plane * R + r]);
    float mx = block_max_256(m, red);
    for (int c = threadIdx.x; c < cols; c += 256) sT[plane * cols + c] = mx;
}

// Transpose+requant from int8 h/l (per-row scales) -> int8 h/l (plane scale in sTarr).
__global__ void transquant_q_kernel(const int8_t* __restrict__ ih, const int8_t* __restrict__ il,
                                    const float* __restrict__ s, const float* __restrict__ sTarr,
                                    int8_t* __restrict__ oh, int8_t* __restrict__ ol,
                                    int rows, int cols) {
    __shared__ float t[32][33];
    long plane = blockIdx.z;
    int c0 = blockIdx.x * 32, r0 = blockIdx.y * 32;
    const int8_t* ph = ih + plane * (long)rows * cols;
    const int8_t* pl = il + plane * (long)rows * cols;
    int lr = threadIdx.x >> 5, lc = threadIdx.x & 31;
    #pragma unroll
    for (int j = 0; j < 4; j++) {
        int r = r0 + lr + j * 8;
        float sr = s[plane * rows + r];
        long idx = (long)r * cols + c0 + lc;
        t[lr + j * 8][lc] = sr * ((float)ph[idx] + (float)pl[idx] * 0.00390625f);
    }
    __syncthreads();
    float sp = sTarr[plane * cols + c0];
    float inv = (sp > 0.0f) ? 1.0f / sp : 0.0f;
    int orow = threadIdx.x >> 3, og = threadIdx.x & 7;
    int c = c0 + orow;
    char hv[4], lv[4];
    #pragma unroll
    for (int j = 0; j < 4; j++) {
        int h, l;
        quant2(t[og * 4 + j][orow] * inv, h, l);
        hv[j] = (char)h; lv[j] = (char)l;
    }
    long o = plane * (long)rows * cols + (long)c * rows + r0 + og * 4;
    *(char4*)(oh + o) = make_char4(hv[0], hv[1], hv[2], hv[3]);
    *(char4*)(ol + o) = make_char4(lv[0], lv[1], lv[2], lv[3]);
}

// Weight transpose+quant (one-time)
__global__ void wtq_kernel(const float* __restrict__ in,
                           int8_t* __restrict__ oh, int8_t* __restrict__ ol,
                           float* __restrict__ os, int Kin, int Nout) {
    extern __shared__ float stash[];
    __shared__ float red[8];
    long plane = blockIdx.y;
    int n = blockIdx.x;
    const float* p = in + plane * (long)Kin * Nout;
    float m = 0.0f;
    for (int k = threadIdx.x; k < Kin; k += 256) {
        float x = p[(long)k * Nout + n];
        stash[k] = x;
        m = fmaxf(m, fabsf(x));
    }
    float s = block_max_256(m, red);
    if (threadIdx.x == 0) os[plane * Nout + n] = s * (1.0f / 127.0f);
    float inv = (s > 0.0f) ? 127.0f / s : 0.0f;
    long o = plane * (long)Nout * Kin + (long)n * Kin;
    for (int k = threadIdx.x; k < Kin; k += 256) {
        int h, l;
        quant2(stash[k] * inv, h, l);
        oh[o + k] = (int8_t)h; ol[o + k] = (int8_t)l;
    }
}

// ---------------------------------------------------------------------------
// Elementwise kernels
// ---------------------------------------------------------------------------
__global__ void rope_tables_kernel(float* cosT, float* sinT) {
    int t = blockIdx.x, j = threadIdx.x;
    double inv = pow(10000.0, -(2.0 * (double)j) / (double)DH);
    double phase = (double)t * inv;
    float c = (float)cos(phase), s = (float)sin(phase);
    cosT[t * DH + j] = c;  cosT[t * DH + 512 + j] = c;
    sinT[t * DH + j] = s;  sinT[t * DH + 512 + j] = s;
}

__global__ void rope_rowquant_kernel(const float* __restrict__ x,
                                     const float* __restrict__ cosT,
                                     const float* __restrict__ sinT,
                                     int8_t* __restrict__ qh, int8_t* __restrict__ ql,
                                     float* __restrict__ qs) {
    __shared__ float red[8];
    long bht = blockIdx.x;
    int t = (int)(bht & (TT - 1));
    const float* xp = x + bht * DH;
    float vals[4];
    float m = 0.0f;
    #pragma unroll
    for (int j = 0; j < 4; j++) {
        int e = threadIdx.x + j * 256;
        float xv = xp[e];
        float ov = (e < 512) ? -xp[e + 512] : xp[e - 512];
        float r = xv * cosT[t * DH + e] + ov * sinT[t * DH + e];
        vals[j] = r;
        m = fmaxf(m, fabsf(r));
    }
    float s = block_max_256(m, red);
    if (threadIdx.x == 0) qs[bht] = s * (1.0f / 127.0f);
    float inv = (s > 0.0f) ? 127.0f / s : 0.0f;
    #pragma unroll
    for (int j = 0; j < 4; j++) {
        int e = threadIdx.x + j * 256;
        int h, l;
        quant2(vals[j] * inv, h, l);
        qh[bht * DH + e] = (int8_t)h;
        ql[bht * DH + e] = (int8_t)l;
    }
}

__global__ void embed_ln_kernel(const int* __restrict__ tokens,
                                const float* __restrict__ emb_w,
                                float* __restrict__ v,
                                int8_t* __restrict__ qh, int8_t* __restrict__ ql,
                                float* __restrict__ qs) {
    __shared__ float smem[8];
    int bt = blockIdx.x, d = threadIdx.x;
    float val = emb_w[tokens[bt] * DD + d];
    float m = block_sum_256(val, smem) * (1.0f / DD);
    float c = val - m;
    float var = block_sum_256(c * c, smem) * (1.0f / DD);
    float r = c * rsqrtf(var + EPS);
    long i = (long)bt * DD + d;
    v[i] = r;
    float s = block_max_256(fabsf(r), smem);
    if (d == 0) qs[bt] = s * (1.0f / 127.0f);
    float inv = (s > 0.0f) ? 127.0f / s : 0.0f;
    int h, l;
    quant2(r * inv, h, l);
    qh[i] = (int8_t)h; ql[i] = (int8_t)l;
}

// v = LN(v + LN(z0+z1)); also emits row-quant of v.
__global__ void fuse_ln2_kernel(const float* __restrict__ z,
                                float* __restrict__ v,
                                int8_t* __restrict__ qh, int8_t* __restrict__ ql,
                                float* __restrict__ qs) {
    __shared__ float smem[8];
    int bt = blockIdx.x, d = threadIdx.x;
    long i = (long)bt * DD + d;
    const long S = (long)BB * TT * DD;
    float u = z[i] + z[i + S];
    float m1 = block_sum_256(u, smem) * (1.0f / DD);
    float c1 = u - m1;
    float var1 = block_sum_256(c1 * c1, smem) * (1.0f / DD);
    float lnz = c1 * rsqrtf(var1 + EPS);
    float w = v[i] + lnz;
    float m2 = block_sum_256(w, smem) * (1.0f / DD);
    float c2 = w - m2;
    float var2 = block_sum_256(c2 * c2, smem) * (1.0f / DD);
    float r = c2 * rsqrtf(var2 + EPS);
    v[i] = r;
    float s = block_max_256(fabsf(r), smem);
    if (d == 0) qs[bt] = s * (1.0f / 127.0f);
    float inv = (s > 0.0f) ? 127.0f / s : 0.0f;
    int h, l;
    quant2(r * inv, h, l);
    qh[i] = (int8_t)h; ql[i] = (int8_t)l;
}

// ---------------------------------------------------------------------------
// Host launcher
// ---------------------------------------------------------------------------
#define GET(sym, var) cudaGetSymbolAddress((void**)&var, sym)

extern "C" void kernel_launch(void* const* d_in, const int* in_sizes, int n_in,
                              void* d_out, int out_size) {
    const int*   tokens  = (const int*)d_in[0];
    const float* emb_w   = (const float*)d_in[1];
    const float* E       = (const float*)d_in[2];
    const float* Dx      = (const float*)d_in[3];
    const float* Dy      = (const float*)d_in[4];
    const float* readout = (const float*)d_in[5];
    float* out = (float*)d_out;

    float *v, *x, *w2, *a, *ye, *zb, *cosT, *sinT;
    GET(g_v, v); GET(g_x, x); GET(g_w2, w2); GET(g_a, a);
    GET(g_ye, ye); GET(g_z, zb); GET(g_cos, cosT); GET(g_sin, sinT);

    int8_t *vqh, *vql, *vTh, *vTl, *xrh, *xrl, *xrTh, *xrTl, *w2h, *w2l;
    int8_t *ah, *al, *yeh, *yel, *dxh, *dxl, *dyh, *dyl, *eh, *el, *roh, *rol;
    GET(q_v_h, vqh); GET(q_v_l, vql); GET(q_vT_h, vTh); GET(q_vT_l, vTl);
    GET(q_xr_h, xrh); GET(q_xr_l, xrl); GET(q_xrT_h, xrTh); GET(q_xrT_l, xrTl);
    GET(q_w2_h, w2h); GET(q_w2_l, w2l); GET(q_a_h, ah); GET(q_a_l, al);
    GET(q_ye_h, yeh); GET(q_ye_l, yel);
    GET(q_dxT_h, dxh); GET(q_dxT_l, dxl); GET(q_dyT_h, dyh); GET(q_dyT_l, dyl);
    GET(q_eT_h, eh); GET(q_eT_l, el); GET(q_roT_h, roh); GET(q_roT_l, rol);

    float *sv, *svT, *sxr, *sxrT, *sw2, *sa, *sye, *sdx, *sdy, *se, *sro;
    GET(sc_v, sv); GET(sc_vT, svT); GET(sc_xr, sxr); GET(sc_xrT, sxrT);
    GET(sc_w2, sw2); GET(sc_a, sa); GET(sc_ye, sye);
    GET(sc_dx, sdx); GET(sc_dy, sdy); GET(sc_e, se); GET(sc_ro, sro);

    cudaFuncSetAttribute(mm_s8_kernel<0>, cudaFuncAttributeMaxDynamicSharedMemorySize, SMEM_SZ);
    cudaFuncSetAttribute(mm_s8_kernel<1>, cudaFuncAttributeMaxDynamicSharedMemorySize, SMEM_SZ);
    cudaFuncSetAttribute(mm_s8_kernel<2>, cudaFuncAttributeMaxDynamicSharedMemorySize, SMEM_SZ);

    rope_tables_kernel<<<TT, 512>>>(cosT, sinT);
    embed_ln_kernel<<<BB * TT, 256>>>(tokens, emb_w, v, vqh, vql, sv);

    // Weight prep (once)
    wtq_kernel<<<dim3(DH, HH), 256, DD * 4>>>(Dx, dxh, dxl, sdx, DD, DH);
    wtq_kernel<<<dim3(DH, HH), 256, DD * 4>>>(Dy, dyh, dyl, sdy, DD, DH);
    wtq_kernel<<<dim3(DD, 1), 256, NN_ * 4>>>(E, eh, el, se, NN_, DD);
    wtq_kernel<<<dim3(VV, 1), 256, DD * 4>>>(readout, roh, rol, sro, DD, VV);

    const long TDh = (long)TT * DH;
    const long TD  = (long)TT * DD;
    const long DDh = (long)DD * DH;
    const long TN  = (long)TT * NN_;

    // vT quant for layer 0
    fill_scaleT_kernel<<<BB, 256>>>(sv, svT, TT, DD);
    transquant_q_kernel<<<dim3(DD / 32, TT / 32, BB), 256>>>(vqh, vql, sv, svT, vTh, vTl, TT, DD);

    for (int l = 0; l < LL; l++) {
        // 1) x = relu(v @ DxT^T): M=T N=Dh K=D
        mm_s8_kernel<1><<<dim3(8, 8, BB * HH), 256, SMEM_SZ>>>(
            vqh, vql, sv, dxh, dxl, sdx, x, nullptr,
            DD, DD, DD, DH, 0,
            HH, TD, 0,   HH, 0, DDh,   1, TDh, 0,   0);

        // 2) RoPE + rowquant
        rope_rowquant_kernel<<<BB * HH * TT, 256>>>(x, cosT, sinT, xrh, xrl, sxr);
        fill_scaleT_kernel<<<BB * HH, 256>>>(sxr, sxrT, TT, DH);
        transquant_q_kernel<<<dim3(DH / 32, TT / 32, BB * HH), 256>>>(
            xrh, xrl, sxr, sxrT, xrTh, xrTl, TT, DH);

        // 3) w2 = vT @ xrT^T: M=D N=Dh K=T
        mm_s8_kernel<0><<<dim3(8, 2, BB * HH), 256, SMEM_SZ>>>(
            vTh, vTl, svT, xrTh, xrTl, sxrT, w2, nullptr,
            TT, TT, TT, DH, 0,
            HH, (long)DD * TT, 0,   1, (long)DH * TT, 0,   1, DDh, 0,   0);
        qrow_kernel<<<BB * HH * DD, 256, DH * 4>>>(w2, w2h, w2l, sw2, DH);

        // 4) a = xr @ w2^T: M=T N=D K=Dh
        mm_s8_kernel<0><<<dim3(2, 8, BB * HH), 256, SMEM_SZ>>>(
            xrh, xrl, sxr, w2h, w2l, sw2, a, nullptr,
            DH, DH, DH, DD, 0,
            1, TDh, 0,   1, DDh, 0,   1, TD, 0,   0);
        qrow_kernel<<<BB * HH * TT, 256, DD * 4>>>(a, ah, al, sa, DD);

        // 5) ye = relu(a @ DyT^T) * x: M=T N=Dh K=D (fp32 AUX)
        mm_s8_kernel<2><<<dim3(8, 8, BB * HH), 256, SMEM_SZ>>>(
            ah, al, sa, dyh, dyl, sdy, ye, x,
            DD, DD, DD, NN_, DH,
            1, TD, 0,   HH, 0, DDh,   HH, TN, DH,   TDh);
        qrow_kernel<<<BB * TT, 256, NN_ * 4>>>(ye, yeh, yel, sye, NN_);

        // 6) z partials (split-K x2): M=B*T N=D K=2048 each
        mm_s8_kernel<0><<<dim3(2, 32, 2), 256, SMEM_SZ>>>(
            yeh, yel, sye, eh, el, se, zb, nullptr,
            NN_ / 2, NN_, NN_, DD, 0,
            1, NN_ / 2, 0,   1, NN_ / 2, 0,   1, (long)BB * TT * DD, 0,   0);

        // 7) v = LN(v + LN(z0+z1)) + rowquant; vT requant
        fuse_ln2_kernel<<<BB * TT, 256>>>(zb, v, vqh, vql, sv);
        fill_scaleT_kernel<<<BB, 256>>>(sv, svT, TT, DD);
        transquant_q_kernel<<<dim3(DD / 32, TT / 32, BB), 256>>>(
            vqh, vql, sv, svT, vTh, vTl, TT, DD);
    }

    // out = v @ roT^T: M=B*T N=V K=D
    mm_s8_kernel<0><<<dim3(2, 32, 1), 256, SMEM_SZ>>>(
        vqh, vql, sv, roh, rol, sro, out, nullptr,
        DD, DD, DD, VV, 0,
        1, 0, 0,   1, 0, 0,   1, 0, 0,   0);
}

// round 15
// speedup vs baseline: 1.0860x; 1.0180x over previous
#include <cuda_runtime.h>
#include <cuda_bf16.h>
#include <math.h>
#include <stdint.h>

#define BB 4
#define TT 1024
#define HH 4
#define NN_ 4096
#define DD 256
#define DH 1024
#define LL 6
#define VV 256
#define EPS 1e-5f

// ---------------------------------------------------------------------------
// Scratch (device globals)
// ---------------------------------------------------------------------------
__device__ float g_v[BB * TT * DD];
__device__ float g_x[BB * HH * TT * DH];
__device__ float g_w2[BB * HH * DD * DH];
__device__ float g_a[BB * HH * TT * DD];
__device__ float g_ye[BB * TT * NN_];
__device__ float g_z[2 * BB * TT * DD];
__device__ float g_cos[TT * DH];
__device__ float g_sin[TT * DH];

// int8 quantized operands (h, l) + per-row scales
__device__ int8_t q_v_h[BB * TT * DD],      q_v_l[BB * TT * DD];
__device__ int8_t q_vT_h[BB * DD * TT],     q_vT_l[BB * DD * TT];
__device__ int8_t q_xr_h[BB * HH * TT * DH], q_xr_l[BB * HH * TT * DH];
__device__ int8_t q_xrT_h[BB * HH * DH * TT], q_xrT_l[BB * HH * DH * TT];
__device__ int8_t q_w2_h[BB * HH * DD * DH], q_w2_l[BB * HH * DD * DH];
__device__ int8_t q_a_h[BB * HH * TT * DD],  q_a_l[BB * HH * TT * DD];
__device__ int8_t q_ye_h[BB * TT * NN_],     q_ye_l[BB * TT * NN_];
__device__ int8_t q_dxT_h[HH * DH * DD],     q_dxT_l[HH * DH * DD];
__device__ int8_t q_dyT_h[HH * DH * DD],     q_dyT_l[HH * DH * DD];
__device__ int8_t q_eT_h[DD * NN_],          q_eT_l[DD * NN_];
__device__ int8_t q_roT_h[VV * DD],          q_roT_l[VV * DD];

__device__ float sc_v[BB * TT];
__device__ float sc_vT[BB * DD];
__device__ float sc_xr[BB * HH * TT];
__device__ float sc_xrT[BB * HH * DH];
__device__ float sc_w2[BB * HH * DD];
__device__ float sc_a[BB * HH * TT];
__device__ float sc_ye[BB * TT];
__device__ float sc_dx[HH * DH];
__device__ float sc_dy[HH * DH];
__device__ float sc_e[DD];
__device__ float sc_ro[VV];

// ---------------------------------------------------------------------------
// PTX helpers
// ---------------------------------------------------------------------------
__device__ __forceinline__ uint32_t smem_to_u32(const void* p) {
    uint32_t a;
    asm("{ .reg .u64 t; cvta.to.shared.u64 t, %1; cvt.u32.u64 %0, t; }" : "=r"(a) : "l"(p));
    return a;
}
__device__ __forceinline__ void cp16(uint32_t dst, const void* src) {
    asm volatile("cp.async.cg.shared.global [%0], [%1], 16;" :: "r"(dst), "l"(src));
}
#define CP_COMMIT() asm volatile("cp.async.commit_group;" ::: "memory")
#define CP_WAIT0() asm volatile("cp.async.wait_group 0;" ::: "memory")
#define CP_WAIT1() asm volatile("cp.async.wait_group 1;" ::: "memory")
#define CP_WAIT2() asm volatile("cp.async.wait_group 2;" ::: "memory")

__device__ __forceinline__ void ldsm_x4(uint32_t* r, uint32_t addr) {
    asm volatile("ldmatrix.sync.aligned.m8n8.x4.shared.b16 {%0,%1,%2,%3}, [%4];"
                 : "=r"(r[0]), "=r"(r[1]), "=r"(r[2]), "=r"(r[3]) : "r"(addr));
}
__device__ __forceinline__ void mma_s8(int* d, const uint32_t* a, const uint32_t* b) {
    asm volatile(
        "mma.sync.aligned.m16n8k32.row.col.s32.s8.s8.s32 "
        "{%0,%1,%2,%3}, {%4,%5,%6,%7}, {%8,%9}, {%0,%1,%2,%3};"
        : "+r"(d[0]), "+r"(d[1]), "+r"(d[2]), "+r"(d[3])
        : "r"(a[0]), "r"(a[1]), "r"(a[2]), "r"(a[3]), "r"(b[0]), "r"(b[1]));
}

__device__ __forceinline__ void quant2(float u, int& h, int& l) {
    h = __float2int_rn(u);
    if (h > 127) h = 127; else if (h < -127) h = -127;
    l = __float2int_rn((u - (float)h) * 256.0f);
    if (l > 127) l = 127; else if (l < -127) l = -127;
}

// ---------------------------------------------------------------------------
// int8 two-level GEMM: C = epi(sA*sB*(A@B^T)), 128x128 CTA tile, 8 warps.
// EPI 0: acc; 1: relu.
// ---------------------------------------------------------------------------
#define TILE_B 8192
#define NBUF 4
#define SMEM_SZ (NBUF * 4 * TILE_B)
__device__ __forceinline__ uint32_t tile_addr(uint32_t sb, int buf, int which) {
    return sb + (uint32_t)((buf * 4 + which) * TILE_B);
}

template <int EPI>
__global__ void __launch_bounds__(256)
mm_s8_kernel(const int8_t* __restrict__ Ah, const int8_t* __restrict__ Al,
             const float* __restrict__ sA,
             const int8_t* __restrict__ Bh, const int8_t* __restrict__ Bl,
             const float* __restrict__ sB,
             float* __restrict__ C,
             int K, int lda, int ldb, int ldc,
             int divA, long strA1, long strA2,
             int divB, long strB1, long strB2,
             int divC, long strC1, long strC2) {
    extern __shared__ char smem[];
    const uint32_t sb = smem_to_u32(smem);
    const int tid = threadIdx.x;
    const int wid = tid >> 5;
    const int lane = tid & 31;
    const int wr = wid >> 2;
    const int wc = wid & 3;
    const int g = lane >> 2;
    const int tig = lane & 3;

    const int z = blockIdx.z;
    const long offA = (long)(z / divA) * strA1 + (long)(z % divA) * strA2;
    const long offB = (long)(z / divB) * strB1 + (long)(z % divB) * strB2;
    Ah += offA; Al += offA; Bh += offB; Bl += offB;
    C += (long)(z / divC) * strC1 + (long)(z % divC) * strC2;
    const long sAoff = (long)(z / divA) * (strA1 / lda) + (long)(z % divA) * (strA2 / lda);
    const long sBoff = (long)(z / divB) * (strB1 / ldb) + (long)(z % divB) * (strB2 / ldb);
    const int rowBase = blockIdx.y * 128;
    const int colBase = blockIdx.x * 128;

    int acc1[4][4][4], acc2[4][4][4];
    #pragma unroll
    for (int i = 0; i < 4; i++)
        #pragma unroll
        for (int j = 0; j < 4; j++)
            #pragma unroll
            for (int k = 0; k < 4; k++) { acc1[i][j][k] = 0; acc2[i][j][k] = 0; }

    const int nStages = K >> 6;

    auto stage = [&](int buf, int c) {
        const int k0 = c << 6;
        #pragma unroll
        for (int i = 0; i < 2; i++) {
            int ch = tid + 256 * i;
            int row = ch >> 2;
            int grp = ch & 3;
            uint32_t dst = (uint32_t)(row * 64 + 16 * (grp ^ ((row >> 1) & 3)));
            long srcA = (long)(rowBase + row) * lda + k0 + grp * 16;
            long srcB = (long)(colBase + row) * ldb + k0 + grp * 16;
            cp16(tile_addr(sb, buf, 0) + dst, Ah + srcA);
            cp16(tile_addr(sb, buf, 1) + dst, Al + srcA);
            cp16(tile_addr(sb, buf, 2) + dst, Bh + srcB);
            cp16(tile_addr(sb, buf, 3) + dst, Bl + srcB);
        }
    };

    auto compute = [&](int buf) {
        #pragma unroll
        for (int s = 0; s < 2; s++) {
            uint32_t afr[2][4][4], bfr[2][4][2];
            #pragma unroll
            for (int hl = 0; hl < 2; hl++) {
                const uint32_t tb = tile_addr(sb, buf, hl);
                const int row0 = wr * 64 + (lane & 7) + 8 * ((lane >> 3) & 1);
                const int grp = 2 * s + (lane >> 4);
                #pragma unroll
                for (int ms = 0; ms < 4; ms++) {
                    int row = row0 + ms * 16;
                    ldsm_x4(&afr[hl][ms][0],
                            tb + (uint32_t)(row * 64 + 16 * (grp ^ ((row >> 1) & 3))));
                }
            }
            #pragma unroll
            for (int hl = 0; hl < 2; hl++) {
                const uint32_t tb = tile_addr(sb, buf, 2 + hl);
                const int nrow0 = wc * 32 + (lane & 7) + 8 * (lane >> 4);
                const int grp = 2 * s + ((lane >> 3) & 1);
                #pragma unroll
                for (int p = 0; p < 2; p++) {
                    int nrow = nrow0 + p * 16;
                    uint32_t r4[4];
                    ldsm_x4(r4, tb + (uint32_t)(nrow * 64 + 16 * (grp ^ ((nrow >> 1) & 3))));
                    bfr[hl][2 * p][0] = r4[0]; bfr[hl][2 * p][1] = r4[1];
                    bfr[hl][2 * p + 1][0] = r4[2]; bfr[hl][2 * p + 1][1] = r4[3];
                }
            }
            #pragma unroll
            for (int ms = 0; ms < 4; ms++)
                #pragma unroll
                for (int ns = 0; ns < 4; ns++)
                    mma_s8(acc1[ms][ns], afr[0][ms], bfr[0][ns]);
            #pragma unroll
            for (int ms = 0; ms < 4; ms++)
                #pragma unroll
                for (int ns = 0; ns < 4; ns++)
                    mma_s8(acc2[ms][ns], afr[0][ms], bfr[1][ns]);
            #pragma unroll
            for (int ms = 0; ms < 4; ms++)
                #pragma unroll
                for (int ns = 0; ns < 4; ns++)
                    mma_s8(acc2[ms][ns], afr[1][ms], bfr[0][ns]);
        }
    };

    stage(0, 0); CP_COMMIT();
    if (nStages > 1) { stage(1, 1); CP_COMMIT(); }
    if (nStages > 2) { stage(2, 2); CP_COMMIT(); }
    int buf = 0;
    for (int c = 0; c < nStages; c++) {
        if (c + 2 < nStages) { CP_WAIT2(); }
        else if (c + 1 < nStages) { CP_WAIT1(); }
        else { CP_WAIT0(); }
        __syncthreads();
        compute(buf);
        if (c + 3 < nStages) {
            int nb = buf + 3; if (nb >= NBUF) nb -= NBUF;
            stage(nb, c + 3);
            CP_COMMIT();
        }
        if (++buf == NBUF) buf = 0;
    }

    #pragma unroll
    for (int ms = 0; ms < 4; ms++) {
        const int r = rowBase + wr * 64 + ms * 16 + g;
        const float sr0 = sA[sAoff + r];
        const float sr1 = sA[sAoff + r + 8];
        #pragma unroll
        for (int ns = 0; ns < 4; ns++) {
            const int col = colBase + wc * 32 + ns * 8 + tig * 2;
            const float sc0 = sB[sBoff + col];
            const float sc1 = sB[sBoff + col + 1];
            float2 v0, v1;
            v0.x = sr0 * sc0 * ((float)acc1[ms][ns][0] + (float)acc2[ms][ns][0] * 0.00390625f);
            v0.y = sr0 * sc1 * ((float)acc1[ms][ns][1] + (float)acc2[ms][ns][1] * 0.00390625f);
            v1.x = sr1 * sc0 * ((float)acc1[ms][ns][2] + (float)acc2[ms][ns][2] * 0.00390625f);
            v1.y = sr1 * sc1 * ((float)acc1[ms][ns][3] + (float)acc2[ms][ns][3] * 0.00390625f);
            if (EPI >= 1) {
                v0.x = fmaxf(v0.x, 0.0f); v0.y = fmaxf(v0.y, 0.0f);
                v1.x = fmaxf(v1.x, 0.0f); v1.y = fmaxf(v1.y, 0.0f);
            }
            *(float2*)(C + (long)r * ldc + col) = v0;
            *(float2*)(C + (long)(r + 8) * ldc + col) = v1;
        }
    }
}

// ---------------------------------------------------------------------------
// Reductions
// ---------------------------------------------------------------------------
__device__ __forceinline__ float block_sum_256(float v, float* smem) {
    #pragma unroll
    for (int o = 16; o > 0; o >>= 1) v += __shfl_down_sync(0xffffffffu, v, o);
    int w = threadIdx.x >> 5, l = threadIdx.x & 31;
    if (l == 0) smem[w] = v;
    __syncthreads();
    if (w == 0) {
        float s = (l < 8) ? smem[l] : 0.0f;
        #pragma unroll
        for (int o = 4; o > 0; o >>= 1) s += __shfl_down_sync(0xffffffffu, s, o);
        if (l == 0) smem[0] = s;
    }
    __syncthreads();
    float r = smem[0];
    __syncthreads();
    return r;
}
__device__ __forceinline__ float block_max_256(float v, float* smem) {
    #pragma unroll
    for (int o = 16; o > 0; o >>= 1) v = fmaxf(v, __shfl_down_sync(0xffffffffu, v, o));
    int w = threadIdx.x >> 5, l = threadIdx.x & 31;
    if (l == 0) smem[w] = v;
    __syncthreads();
    if (w == 0) {
        float s = (l < 8) ? smem[l] : 0.0f;
        #pragma unroll
        for (int o = 4; o > 0; o >>= 1) s = fmaxf(s, __shfl_down_sync(0xffffffffu, s, o));
        if (l == 0) smem[0] = s;
    }
    __syncthreads();
    float r = smem[0];
    __syncthreads();
    return r;
}

// ---------------------------------------------------------------------------
// Quantization kernels
// ---------------------------------------------------------------------------
__global__ void qrow_kernel(const float* __restrict__ in,
                            int8_t* __restrict__ oh, int8_t* __restrict__ ol,
                            float* __restrict__ os, int K) {
    extern __shared__ float stash[];
    __shared__ float red[8];
    long row = blockIdx.x;
    const float4* p = (const float4*)(in + row * K);
    int n4 = K >> 2;
    float m = 0.0f;
    for (int i = threadIdx.x; i < n4; i += 256) {
        float4 v = p[i];
        ((float4*)stash)[i] = v;
        m = fmaxf(m, fmaxf(fmaxf(fabsf(v.x), fabsf(v.y)), fmaxf(fabsf(v.z), fabsf(v.w))));
    }
    float s = block_max_256(m, red);
    if (threadIdx.x == 0) os[row] = s * (1.0f / 127.0f);
    float inv = (s > 0.0f) ? 127.0f / s : 0.0f;
    for (int i = threadIdx.x; i < n4; i += 256) {
        float4 v = ((float4*)stash)[i];
        int h0, l0, h1, l1, h2, l2, h3, l3;
        quant2(v.x * inv, h0, l0); quant2(v.y * inv, h1, l1);
        quant2(v.z * inv, h2, l2); quant2(v.w * inv, h3, l3);
        ((char4*)(oh + row * K))[i] = make_char4((char)h0, (char)h1, (char)h2, (char)h3);
        ((char4*)(ol + row * K))[i] = make_char4((char)l0, (char)l1, (char)l2, (char)l3);
    }
}

// ye finalize: block per (b,t) row. Reads raw relu-GEMM output row [4096]
// (layout [b, t, h*Dh+e]) and x segments (layout [b,h,t,e]); multiplies,
// rowmax, quantizes to q_ye h/l + scale. Bit-identical to the old
// GEMM-epilogue-multiply + qrow pipeline.
__global__ void qrow_mulx_kernel(const float* __restrict__ ye_raw,
                                 const float* __restrict__ x,
                                 int8_t* __restrict__ oh, int8_t* __restrict__ ol,
                                 float* __restrict__ os) {
    extern __shared__ float stash[];
    __shared__ float red[8];
    long bt = blockIdx.x;               // b*T + t
    long b = bt >> 10;
    long t = bt & (TT - 1);
    const float4* pye = (const float4*)(ye_raw + bt * NN_);
    float m = 0.0f;
    #pragma unroll
    for (int hseg = 0; hseg < HH; hseg++) {
        const float4* px = (const float4*)(x + (((b * HH + hseg) * TT + t) * DH));
        for (int i = threadIdx.x; i < DH / 4; i += 256) {
            float4 vy = pye[hseg * (DH / 4) + i];
            float4 vx = px[i];
            vy.x *= vx.x; vy.y *= vx.y; vy.z *= vx.z; vy.w *= vx.w;
            ((float4*)stash)[hseg * (DH / 4) + i] = vy;
            m = fmaxf(m, fmaxf(fmaxf(fabsf(vy.x), fabsf(vy.y)),
                               fmaxf(fabsf(vy.z), fabsf(vy.w))));
        }
    }
    float s = block_max_256(m, red);
    if (threadIdx.x == 0) os[bt] = s * (1.0f / 127.0f);
    float inv = (s > 0.0f) ? 127.0f / s : 0.0f;
    for (int i = threadIdx.x; i < NN_ / 4; i += 256) {
        float4 v = ((float4*)stash)[i];
        int h0, l0, h1, l1, h2, l2, h3, l3;
        quant2(v.x * inv, h0, l0); quant2(v.y * inv, h1, l1);
        quant2(v.z * inv, h2, l2); quant2(v.w * inv, h3, l3);
        ((char4*)(oh + bt * NN_))[i] = make_char4((char)h0, (char)h1, (char)h2, (char)h3);
        ((char4*)(ol + bt * NN_))[i] = make_char4((char)l0, (char)l1, (char)l2, (char)l3);
    }
}

// Fill transposed-plane scales: sT[plane*cols + c] = max_r s[plane*R + r]
__global__ void fill_scaleT_kernel(const float* __restrict__ s, float* __restrict__ sT,
                                   int R, int cols) {
    __shared__ float red[8];
    long plane = blockIdx.x;
    float m = 0.0f;
    for (int r = threadIdx.x; r < R; r += 256) m = fmaxf(m, s[plane * R + r]);
    float mx = block_max_256(m, red);
    for (int c = threadIdx.x; c < cols; c += 256) sT[plane * cols + c] = mx;
}

// Transpose+requant from int8 h/l (per-row scales) -> int8 h/l (plane scale in sTarr).
__global__ void transquant_q_kernel(const int8_t* __restrict__ ih, const int8_t* __restrict__ il,
                                    const float* __restrict__ s, const float* __restrict__ sTarr,
                                    int8_t* __restrict__ oh, int8_t* __restrict__ ol,
                                    int rows, int cols) {
    __shared__ float t[32][33];
    long plane = blockIdx.z;
    int c0 = blockIdx.x * 32, r0 = blockIdx.y * 32;
    const int8_t* ph = ih + plane * (long)rows * cols;
    const int8_t* pl = il + plane * (long)rows * cols;
    int lr = threadIdx.x >> 5, lc = threadIdx.x & 31;
    #pragma unroll
    for (int j = 0; j < 4; j++) {
        int r = r0 + lr + j * 8;
        float sr = s[plane * rows + r];
        long idx = (long)r * cols + c0 + lc;
        t[lr + j * 8][lc] = sr * ((float)ph[idx] + (float)pl[idx] * 0.00390625f);
    }
    __syncthreads();
    float sp = sTarr[plane * cols + c0];
    float inv = (sp > 0.0f) ? 1.0f / sp : 0.0f;
    int orow = threadIdx.x >> 3, og = threadIdx.x & 7;
    int c = c0 + orow;
    char hv[4], lv[4];
    #pragma unroll
    for (int j = 0; j < 4; j++) {
        int h, l;
        quant2(t[og * 4 + j][orow] * inv, h, l);
        hv[j] = (char)h; lv[j] = (char)l;
    }
    long o = plane * (long)rows * cols + (long)c * rows + r0 + og * 4;
    *(char4*)(oh + o) = make_char4(hv[0], hv[1], hv[2], hv[3]);
    *(char4*)(ol + o) = make_char4(lv[0], lv[1], lv[2], lv[3]);
}

// Weight transpose+quant (one-time)
__global__ void wtq_kernel(const float* __restrict__ in,
                           int8_t* __restrict__ oh, int8_t* __restrict__ ol,
                           float* __restrict__ os, int Kin, int Nout) {
    extern __shared__ float stash[];
    __shared__ float red[8];
    long plane = blockIdx.y;
    int n = blockIdx.x;
    const float* p = in + plane * (long)Kin * Nout;
    float m = 0.0f;
    for (int k = threadIdx.x; k < Kin; k += 256) {
        float x = p[(long)k * Nout + n];
        stash[k] = x;
        m = fmaxf(m, fabsf(x));
    }
    float s = block_max_256(m, red);
    if (threadIdx.x == 0) os[plane * Nout + n] = s * (1.0f / 127.0f);
    float inv = (s > 0.0f) ? 127.0f / s : 0.0f;
    long o = plane * (long)Nout * Kin + (long)n * Kin;
    for (int k = threadIdx.x; k < Kin; k += 256) {
        int h, l;
        quant2(stash[k] * inv, h, l);
        oh[o + k] = (int8_t)h; ol[o + k] = (int8_t)l;
    }
}

// ---------------------------------------------------------------------------
// Elementwise kernels
// ---------------------------------------------------------------------------
__global__ void rope_tables_kernel(float* cosT, float* sinT) {
    int t = blockIdx.x, j = threadIdx.x;
    double inv = pow(10000.0, -(2.0 * (double)j) / (double)DH);
    double phase = (double)t * inv;
    float c = (float)cos(phase), s = (float)sin(phase);
    cosT[t * DH + j] = c;  cosT[t * DH + 512 + j] = c;
    sinT[t * DH + j] = s;  sinT[t * DH + 512 + j] = s;
}

__global__ void rope_rowquant_kernel(const float* __restrict__ x,
                                     const float* __restrict__ cosT,
                                     const float* __restrict__ sinT,
                                     int8_t* __restrict__ qh, int8_t* __restrict__ ql,
                                     float* __restrict__ qs) {
    __shared__ float red[8];
    long bht = blockIdx.x;
    int t = (int)(bht & (TT - 1));
    const float* xp = x + bht * DH;
    float vals[4];
    float m = 0.0f;
    #pragma unroll
    for (int j = 0; j < 4; j++) {
        int e = threadIdx.x + j * 256;
        float xv = xp[e];
        float ov = (e < 512) ? -xp[e + 512] : xp[e - 512];
        float r = xv * cosT[t * DH + e] + ov * sinT[t * DH + e];
        vals[j] = r;
        m = fmaxf(m, fabsf(r));
    }
    float s = block_max_256(m, red);
    if (threadIdx.x == 0) qs[bht] = s * (1.0f / 127.0f);
    float inv = (s > 0.0f) ? 127.0f / s : 0.0f;
    #pragma unroll
    for (int j = 0; j < 4; j++) {
        int e = threadIdx.x + j * 256;
        int h, l;
        quant2(vals[j] * inv, h, l);
        qh[bht * DH + e] = (int8_t)h;
        ql[bht * DH + e] = (int8_t)l;
    }
}

__global__ void embed_ln_kernel(const int* __restrict__ tokens,
                                const float* __restrict__ emb_w,
                                float* __restrict__ v,
                                int8_t* __restrict__ qh, int8_t* __restrict__ ql,
                                float* __restrict__ qs) {
    __shared__ float smem[8];
    int bt = blockIdx.x, d = threadIdx.x;
    float val = emb_w[tokens[bt] * DD + d];
    float m = block_sum_256(val, smem) * (1.0f / DD);
    float c = val - m;
    float var = block_sum_256(c * c, smem) * (1.0f / DD);
    float r = c * rsqrtf(var + EPS);
    long i = (long)bt * DD + d;
    v[i] = r;
    float s = block_max_256(fabsf(r), smem);
    if (d == 0) qs[bt] = s * (1.0f / 127.0f);
    float inv = (s > 0.0f) ? 127.0f / s : 0.0f;
    int h, l;
    quant2(r * inv, h, l);
    qh[i] = (int8_t)h; ql[i] = (int8_t)l;
}

// v = LN(v + LN(z0+z1)); also emits row-quant of v.
__global__ void fuse_ln2_kernel(const float* __restrict__ z,
                                float* __restrict__ v,
                                int8_t* __restrict__ qh, int8_t* __restrict__ ql,
                                float* __restrict__ qs) {
    __shared__ float smem[8];
    int bt = blockIdx.x, d = threadIdx.x;
    long i = (long)bt * DD + d;
    const long S = (long)BB * TT * DD;
    float u = z[i] + z[i + S];
    float m1 = block_sum_256(u, smem) * (1.0f / DD);
    float c1 = u - m1;
    float var1 = block_sum_256(c1 * c1, smem) * (1.0f / DD);
    float lnz = c1 * rsqrtf(var1 + EPS);
    float w = v[i] + lnz;
    float m2 = block_sum_256(w, smem) * (1.0f / DD);
    float c2 = w - m2;
    float var2 = block_sum_256(c2 * c2, smem) * (1.0f / DD);
    float r = c2 * rsqrtf(var2 + EPS);
    v[i] = r;
    float s = block_max_256(fabsf(r), smem);
    if (d == 0) qs[bt] = s * (1.0f / 127.0f);
    float inv = (s > 0.0f) ? 127.0f / s : 0.0f;
    int h, l;
    quant2(r * inv, h, l);
    qh[i] = (int8_t)h; ql[i] = (int8_t)l;
}

// ---------------------------------------------------------------------------
// Host launcher
// ---------------------------------------------------------------------------
#define GET(sym, var) cudaGetSymbolAddress((void**)&var, sym)

extern "C" void kernel_launch(void* const* d_in, const int* in_sizes, int n_in,
                              void* d_out, int out_size) {
    const int*   tokens  = (const int*)d_in[0];
    const float* emb_w   = (const float*)d_in[1];
    const float* E       = (const float*)d_in[2];
    const float* Dx      = (const float*)d_in[3];
    const float* Dy      = (const float*)d_in[4];
    const float* readout = (const float*)d_in[5];
    float* out = (float*)d_out;

    float *v, *x, *w2, *a, *ye, *zb, *cosT, *sinT;
    GET(g_v, v); GET(g_x, x); GET(g_w2, w2); GET(g_a, a);
    GET(g_ye, ye); GET(g_z, zb); GET(g_cos, cosT); GET(g_sin, sinT);

    int8_t *vqh, *vql, *vTh, *vTl, *xrh, *xrl, *xrTh, *xrTl, *w2h, *w2l;
    int8_t *ah, *al, *yeh, *yel, *dxh, *dxl, *dyh, *dyl, *eh, *el, *roh, *rol;
    GET(q_v_h, vqh); GET(q_v_l, vql); GET(q_vT_h, vTh); GET(q_vT_l, vTl);
    GET(q_xr_h, xrh); GET(q_xr_l, xrl); GET(q_xrT_h, xrTh); GET(q_xrT_l, xrTl);
    GET(q_w2_h, w2h); GET(q_w2_l, w2l); GET(q_a_h, ah); GET(q_a_l, al);
    GET(q_ye_h, yeh); GET(q_ye_l, yel);
    GET(q_dxT_h, dxh); GET(q_dxT_l, dxl); GET(q_dyT_h, dyh); GET(q_dyT_l, dyl);
    GET(q_eT_h, eh); GET(q_eT_l, el); GET(q_roT_h, roh); GET(q_roT_l, rol);

    float *sv, *svT, *sxr, *sxrT, *sw2, *sa, *sye, *sdx, *sdy, *se, *sro;
    GET(sc_v, sv); GET(sc_vT, svT); GET(sc_xr, sxr); GET(sc_xrT, sxrT);
    GET(sc_w2, sw2); GET(sc_a, sa); GET(sc_ye, sye);
    GET(sc_dx, sdx); GET(sc_dy, sdy); GET(sc_e, se); GET(sc_ro, sro);

    cudaFuncSetAttribute(mm_s8_kernel<0>, cudaFuncAttributeMaxDynamicSharedMemorySize, SMEM_SZ);
    cudaFuncSetAttribute(mm_s8_kernel<1>, cudaFuncAttributeMaxDynamicSharedMemorySize, SMEM_SZ);

    rope_tables_kernel<<<TT, 512>>>(cosT, sinT);
    embed_ln_kernel<<<BB * TT, 256>>>(tokens, emb_w, v, vqh, vql, sv);

    // Weight prep (once)
    wtq_kernel<<<dim3(DH, HH), 256, DD * 4>>>(Dx, dxh, dxl, sdx, DD, DH);
    wtq_kernel<<<dim3(DH, HH), 256, DD * 4>>>(Dy, dyh, dyl, sdy, DD, DH);
    wtq_kernel<<<dim3(DD, 1), 256, NN_ * 4>>>(E, eh, el, se, NN_, DD);
    wtq_kernel<<<dim3(VV, 1), 256, DD * 4>>>(readout, roh, rol, sro, DD, VV);

    const long TDh = (long)TT * DH;
    const long TD  = (long)TT * DD;
    const long DDh = (long)DD * DH;
    const long TN  = (long)TT * NN_;

    // vT quant for layer 0
    fill_scaleT_kernel<<<BB, 256>>>(sv, svT, TT, DD);
    transquant_q_kernel<<<dim3(DD / 32, TT / 32, BB), 256>>>(vqh, vql, sv, svT, vTh, vTl, TT, DD);

    for (int l = 0; l < LL; l++) {
        // 1) x = relu(v @ DxT^T): M=T N=Dh K=D
        mm_s8_kernel<1><<<dim3(8, 8, BB * HH), 256, SMEM_SZ>>>(
            vqh, vql, sv, dxh, dxl, sdx, x,
            DD, DD, DD, DH,
            HH, TD, 0,   HH, 0, DDh,   1, TDh, 0);

        // 2) RoPE + rowquant
        rope_rowquant_kernel<<<BB * HH * TT, 256>>>(x, cosT, sinT, xrh, xrl, sxr);
        fill_scaleT_kernel<<<BB * HH, 256>>>(sxr, sxrT, TT, DH);
        transquant_q_kernel<<<dim3(DH / 32, TT / 32, BB * HH), 256>>>(
            xrh, xrl, sxr, sxrT, xrTh, xrTl, TT, DH);

        // 3) w2 = vT @ xrT^T: M=D N=Dh K=T
        mm_s8_kernel<0><<<dim3(8, 2, BB * HH), 256, SMEM_SZ>>>(
            vTh, vTl, svT, xrTh, xrTl, sxrT, w2,
            TT, TT, TT, DH,
            HH, (long)DD * TT, 0,   1, (long)DH * TT, 0,   1, DDh, 0);
        qrow_kernel<<<BB * HH * DD, 256, DH * 4>>>(w2, w2h, w2l, sw2, DH);

        // 4) a = xr @ w2^T: M=T N=D K=Dh
        mm_s8_kernel<0><<<dim3(2, 8, BB * HH), 256, SMEM_SZ>>>(
            xrh, xrl, sxr, w2h, w2l, sw2, a,
            DH, DH, DH, DD,
            1, TDh, 0,   1, DDh, 0,   1, TD, 0);
        qrow_kernel<<<BB * HH * TT, 256, DD * 4>>>(a, ah, al, sa, DD);

        // 5) ye_raw = relu(a @ DyT^T): M=T N=Dh K=D (no AUX in epilogue)
        mm_s8_kernel<1><<<dim3(8, 8, BB * HH), 256, SMEM_SZ>>>(
            ah, al, sa, dyh, dyl, sdy, ye,
            DD, DD, DD, NN_,
            1, TD, 0,   HH, 0, DDh,   HH, TN, DH);
        // multiply by x + rowquant (coalesced)
        qrow_mulx_kernel<<<BB * TT, 256, NN_ * 4>>>(ye, x, yeh, yel, sye);

        // 6) z partials (split-K x2): M=B*T N=D K=2048 each
        mm_s8_kernel<0><<<dim3(2, 32, 2), 256, SMEM_SZ>>>(
            yeh, yel, sye, eh, el, se, zb,
            NN_ / 2, NN_, NN_, DD,
            1, NN_ / 2, 0,   1, NN_ / 2, 0,   1, (long)BB * TT * DD, 0);

        // 7) v = LN(v + LN(z0+z1)) + rowquant; vT requant
        fuse_ln2_kernel<<<BB * TT, 256>>>(zb, v, vqh, vql, sv);
        fill_scaleT_kernel<<<BB, 256>>>(sv, svT, TT, DD);
        transquant_q_kernel<<<dim3(DD / 32, TT / 32, BB), 256>>>(
            vqh, vql, sv, svT, vTh, vTl, TT, DD);
    }

    // out = v @ roT^T: M=B*T N=V K=D
    mm_s8_kernel<0><<<dim3(2, 32, 1), 256, SMEM_SZ>>>(
        vqh, vql, sv, roh, rol, sro, out,
        DD, DD, DD, VV,
        1, 0, 0,   1, 0, 0,   1, 0, 0);
}